// round 5
// baseline (speedup 1.0000x reference)
#include <cuda_runtime.h>
#include <cuda_bf16.h>
#include <cstring>
#include <cstdint>

#define N_NODES 5000
#define N_EDGES 30000
#define HID     64      // hidden
#define ED      16      // edge dim
#define H2      4096    // hidden^2
#define NCOLS   262144  // 4096*64 columns of M

// ---------------- static device scratch (no allocs allowed) ----------------
// Host shadow symbols exist for every __device__ global: keep total < ~1.6 GB
// or the host link fails (GOTPCREL overflow).
#define PASS_NODES 1024
#define N_PASSES   ((N_NODES + PASS_NODES - 1) / PASS_NODES)   // 5
__device__ __align__(16) float g_M[(size_t)PASS_NODES * NCOLS];   // 1.07 GB
__device__ __align__(16) float g_hid[(size_t)N_EDGES * H2];       // 491.5 MB

__device__ int g_off[N_NODES + 1];
__device__ int g_perm[N_EDGES];

// ---------------- tf32 helpers ----------------
__device__ __forceinline__ uint32_t tf32_rna(float x) {
    uint32_t u;
    asm("cvt.rna.tf32.f32 %0, %1;" : "=r"(u) : "f"(x));
    return u;
}

__device__ __forceinline__ void mma_tf32(float* c,
                                         uint32_t a0, uint32_t a1,
                                         uint32_t a2, uint32_t a3,
                                         uint32_t b0, uint32_t b1) {
    asm volatile(
        "mma.sync.aligned.m16n8k8.row.col.f32.tf32.tf32.f32 "
        "{%0,%1,%2,%3},{%4,%5,%6,%7},{%8,%9},{%0,%1,%2,%3};"
        : "+f"(c[0]), "+f"(c[1]), "+f"(c[2]), "+f"(c[3])
        : "r"(a0), "r"(a1), "r"(a2), "r"(a3), "r"(b0), "r"(b1));
}

// ---------------- fused single-block CSR build ----------------
__global__ void __launch_bounds__(1024) k_csr(const int* __restrict__ ei) {
    __shared__ int scnt[N_NODES];   // 20 KB
    __shared__ int ts[1024];
    int t = threadIdx.x;

    for (int i = t; i < N_NODES; i += 1024) scnt[i] = 0;
    __syncthreads();
    for (int e = t; e < N_EDGES; e += 1024) atomicAdd(&scnt[ei[e]], 1);
    __syncthreads();

    int c[5];
    int base = t * 5;
    int s = 0;
#pragma unroll
    for (int u = 0; u < 5; u++) {
        int id = base + u;
        c[u] = (id < N_NODES) ? scnt[id] : 0;
        s += c[u];
    }
    ts[t] = s;
    __syncthreads();
    for (int ofs = 1; ofs < 1024; ofs <<= 1) {
        int v = (t >= ofs) ? ts[t - ofs] : 0;
        __syncthreads();
        ts[t] += v;
        __syncthreads();
    }
    int ex = ts[t] - s;   // exclusive prefix
#pragma unroll
    for (int u = 0; u < 5; u++) {
        int id = base + u;
        if (id < N_NODES) { g_off[id] = ex; scnt[id] = ex; }   // scnt = cursor
        ex += c[u];
    }
    if (t == 0) g_off[N_NODES] = N_EDGES;
    __syncthreads();
    for (int e = t; e < N_EDGES; e += 1024) {
        int pos = atomicAdd(&scnt[ei[e]], 1);
        g_perm[pos] = e;
    }
}

// ---------------- hid = relu(edge_attr @ W1 + b1) ----------------
#define HID_EB 8
__global__ void k_hid(const float* __restrict__ ea,
                      const float* __restrict__ W1,
                      const float* __restrict__ b1) {
    __shared__ float eaS[HID_EB][ED];
    int e0 = blockIdx.x * HID_EB;
    int tid = threadIdx.x;
    if (tid < HID_EB * ED) {
        int e = tid / ED, t = tid % ED;
        eaS[e][t] = ea[(size_t)(e0 + e) * ED + t];
    }
    __syncthreads();
    for (int k = tid; k < H2; k += 256) {
        float acc[HID_EB];
        float bv = b1[k];
#pragma unroll
        for (int e = 0; e < HID_EB; e++) acc[e] = bv;
#pragma unroll
        for (int t = 0; t < ED; t++) {
            float w = W1[t * H2 + k];
#pragma unroll
            for (int e = 0; e < HID_EB; e++) acc[e] = fmaf(eaS[e][t], w, acc[e]);
        }
#pragma unroll
        for (int e = 0; e < HID_EB; e++)
            __stcs(&g_hid[(size_t)(e0 + e) * H2 + k], fmaxf(acc[e], 0.0f));
    }
}

// ---------------- GEMM1 (tensor-core 3xtf32), tile 128 nodes x 128 cols ----------------
// M[n, c] = sum_j h[n,j] * W2flat[c*64 + j],  exact via split-tf32:
//   x = hi + lo; A*B ~= Ah*Bh + Ah*Bl + Al*Bh  (Al*Bl ~2^-22, negligible)
// smem fragment-ordered tiles: one LDS.128 per lane = full mma fragment.
//   BF[ntile16][ks8][lane32] float4(b0h,b1h,b0l,b1l)  64 KB
//   AH/AL[mtile8][ks8][lane32] float4(a0..a3)         32+32 KB
#define G1_TN 128
#define G1_TC 128
#define G1_SMEM (32768 * 4)   // 128 KB

__global__ void __launch_bounds__(512, 1) k_gemm1(const float* __restrict__ h,
                                                  const float* __restrict__ W2,
                                                  int n_base) {
    extern __shared__ float sm[];
    float* BF = sm;              // 16384 floats
    float* AH = sm + 16384;      // 8192 floats
    float* AL = sm + 24576;      // 8192 floats

    int tid = threadIdx.x;
    int n0 = n_base + blockIdx.y * G1_TN;
    size_t c0 = (size_t)blockIdx.x * G1_TC;

    // ---- fill B fragments (128 cols x 64 j), converted ONCE per block ----
    for (int idx = tid; idx < G1_TC * 64; idx += 512) {
        int c = idx >> 6, j = idx & 63;
        float v = W2[(c0 + c) * 64 + j];
        float hi = __uint_as_float(tf32_rna(v));
        float lo = __uint_as_float(tf32_rna(v - hi));
        int nt = c >> 3, gid = c & 7;
        int ks = j >> 3, jj = j & 7;
        int tig = jj & 3, slot = jj >> 2;
        int fi = (((nt << 3) + ks) * 32 + (gid << 2) + tig) << 2;
        BF[fi + slot]     = hi;
        BF[fi + 2 + slot] = lo;
    }
    // ---- fill A fragments (128 nodes x 64 j) ----
    for (int idx = tid; idx < G1_TN * 64; idx += 512) {
        int m = idx >> 6, j = idx & 63;
        int n = n0 + m;
        float v = (n < N_NODES) ? h[(size_t)n * 64 + j] : 0.0f;
        float hi = __uint_as_float(tf32_rna(v));
        float lo = __uint_as_float(tf32_rna(v - hi));
        int mt = m >> 4, mm = m & 15;
        int ks = j >> 3, jj = j & 7;
        int reg = (mm >> 3) | ((jj >> 2) << 1);
        int lane = ((mm & 7) << 2) + (jj & 3);
        int ai = ((((mt << 3) + ks) * 32 + lane) << 2) | reg;
        AH[ai] = hi;
        AL[ai] = lo;
    }
    __syncthreads();

    int w = tid >> 5, lane = tid & 31;
    int mt = w >> 1;           // m-tile 0..7 (16 nodes each)
    int nh = w & 1;            // col half (64 cols each)

    float acc[8][4];
#pragma unroll
    for (int nt = 0; nt < 8; nt++)
#pragma unroll
        for (int r = 0; r < 4; r++) acc[nt][r] = 0.0f;

#pragma unroll
    for (int ks = 0; ks < 8; ks++) {
        float4 ah = *(const float4*)&AH[(((mt << 3) + ks) * 32 + lane) << 2];
        float4 al = *(const float4*)&AL[(((mt << 3) + ks) * 32 + lane) << 2];
        uint32_t ah0 = __float_as_uint(ah.x), ah1 = __float_as_uint(ah.y);
        uint32_t ah2 = __float_as_uint(ah.z), ah3 = __float_as_uint(ah.w);
        uint32_t al0 = __float_as_uint(al.x), al1 = __float_as_uint(al.y);
        uint32_t al2 = __float_as_uint(al.z), al3 = __float_as_uint(al.w);
#pragma unroll
        for (int nt = 0; nt < 8; nt++) {
            int ntg = (nh << 3) + nt;
            float4 b = *(const float4*)&BF[((((ntg << 3) + ks) << 5) + lane) << 2];
            uint32_t b0h = __float_as_uint(b.x), b1h = __float_as_uint(b.y);
            uint32_t b0l = __float_as_uint(b.z), b1l = __float_as_uint(b.w);
            mma_tf32(acc[nt], ah0, ah1, ah2, ah3, b0h, b1h);   // Ah*Bh
            mma_tf32(acc[nt], ah0, ah1, ah2, ah3, b0l, b1l);   // Ah*Bl
            mma_tf32(acc[nt], al0, al1, al2, al3, b0h, b1h);   // Al*Bh
        }
    }

    // ---- epilogue: streaming stores to g_M ----
    int gid = lane >> 2, tig = lane & 3;
    int row0 = (n0 - n_base) + (mt << 4) + gid;
#pragma unroll
    for (int nt = 0; nt < 8; nt++) {
        size_t col = c0 + (nh << 6) + (nt << 3) + (tig << 1);
        float* p0 = g_M + (size_t)row0 * NCOLS + col;
        __stcs((float2*)p0, make_float2(acc[nt][0], acc[nt][1]));
        __stcs((float2*)(p0 + (size_t)8 * NCOLS),
               make_float2(acc[nt][2], acc[nt][3]));
    }
}

// ---------------- Stage 2: m[e,i] = sum_k hid[e,k]*M[n,k*64+i] + cb[i] ----------------
// 256 threads = 8 edge slots x 32 lanes. 24 edges per M pass, but the inner
// loop is tier-specialized (1/2/3 accumulators) by a warp-uniform branch so
// low-degree nodes issue no dead predicated FMAs.
#define S2_BODY(NACC)                                                         \
    _Pragma("unroll 4")                                                       \
    for (int k = 0; k < 128; k++) {                                           \
        float2 mm = *(const float2*)&Ms[k * 64 + i2];                         \
        float h0 = hidS[s * 128 + k];                                         \
        a0.x = fmaf(h0, mm.x, a0.x);                                          \
        a0.y = fmaf(h0, mm.y, a0.y);                                          \
        if (NACC > 1) {                                                       \
            float h1 = hidS[(s + 8) * 128 + k];                               \
            a1.x = fmaf(h1, mm.x, a1.x);                                      \
            a1.y = fmaf(h1, mm.y, a1.y);                                      \
        }                                                                     \
        if (NACC > 2) {                                                       \
            float h2v = hidS[(s + 16) * 128 + k];                             \
            a2.x = fmaf(h2v, mm.x, a2.x);                                     \
            a2.y = fmaf(h2v, mm.y, a2.y);                                     \
        }                                                                     \
    }

__global__ void __launch_bounds__(256) k_stage2(const float* __restrict__ h,
                                                const float* __restrict__ b2,
                                                float* __restrict__ out,
                                                int n_base) {
    __shared__ __align__(16) float Ms[128 * 64];     // 32 KB M chunk [k][i]
    __shared__ __align__(16) float hidS[24 * 128];   // 12 KB hid chunk
    __shared__ float hS[64];
    __shared__ float cb[64];
    __shared__ int eS[24];

    int n = n_base + blockIdx.x;
    if (n >= N_NODES) return;
    int start = g_off[n], end = g_off[n + 1];
    if (start == end) return;

    int tid = threadIdx.x;
    int s = tid >> 5;
    int il = tid & 31;
    int i2 = il * 2;

    if (tid < 64) hS[tid] = h[(size_t)n * 64 + tid];
    __syncthreads();
    if (s == 0) {
        float c0 = 0.f, c1 = 0.f;
#pragma unroll 8
        for (int j = 0; j < 64; j++) {
            float hv = hS[j];
            c0 = fmaf(b2[i2 * 64 + j], hv, c0);
            c1 = fmaf(b2[(i2 + 1) * 64 + j], hv, c1);
        }
        cb[i2] = c0; cb[i2 + 1] = c1;
    }

    const float* Mrow = g_M + (size_t)(n - n_base) * NCOLS;

    for (int base = start; base < end; base += 24) {
        int cnt = min(24, end - base);
        __syncthreads();
        if (tid < cnt) eS[tid] = g_perm[base + tid];
        __syncthreads();

        float2 a0 = make_float2(cb[i2], cb[i2 + 1]);
        float2 a1 = a0, a2 = a0;
        int nacc = (s < cnt) + (s + 8 < cnt) + (s + 16 < cnt);

        for (int kc = 0; kc < 32; kc++) {
            __syncthreads();
            const float4* msrc = (const float4*)(Mrow + (size_t)kc * 8192);
            for (int u = tid; u < 2048; u += 256)
                ((float4*)Ms)[u] = __ldcs(msrc + u);
            for (int u = tid; u < cnt * 32; u += 256) {
                int v = u >> 5, q = u & 31;
                const float4* hsrc =
                    (const float4*)(g_hid + (size_t)eS[v] * H2 + kc * 128);
                ((float4*)(hidS + v * 128))[q] = __ldcs(hsrc + q);
            }
            __syncthreads();
            switch (nacc) {
                case 1: { S2_BODY(1) } break;
                case 2: { S2_BODY(2) } break;
                case 3: { S2_BODY(3) } break;
                default: break;
            }
        }
        if (nacc > 0) *(float2*)&out[(size_t)eS[s] * 64 + i2] = a0;
        if (nacc > 1) *(float2*)&out[(size_t)eS[s + 8] * 64 + i2] = a1;
        if (nacc > 2) *(float2*)&out[(size_t)eS[s + 16] * 64 + i2] = a2;
    }
}

// ---------------- dst passthrough ----------------
__global__ void k_dst(const int* __restrict__ ei, float* __restrict__ out) {
    int e = blockIdx.x * blockDim.x + threadIdx.x;
    if (e < N_EDGES) out[(size_t)N_EDGES * 64 + e] = (float)ei[N_EDGES + e];
}

// ---------------- launch ----------------
extern "C" void kernel_launch(void* const* d_in, const int* in_sizes, int n_in,
                              void* d_out, int out_size) {
    const float* h  = (const float*)d_in[0];
    const int*   ei = (const int*)d_in[1];
    const float* ea = (const float*)d_in[2];
    const float* W1 = (const float*)d_in[3];
    const float* b1 = (const float*)d_in[4];
    const float* W2 = (const float*)d_in[5];
    const float* b2 = (const float*)d_in[6];
    float* out = (float*)d_out;

    k_csr<<<1, 1024>>>(ei);
    k_hid<<<N_EDGES / HID_EB, 256>>>(ea, W1, b1);

    cudaFuncSetAttribute(k_gemm1, cudaFuncAttributeMaxDynamicSharedMemorySize,
                         G1_SMEM);

    for (int p = 0; p < N_PASSES; p++) {
        int n_base = p * PASS_NODES;
        dim3 g1(NCOLS / G1_TC, PASS_NODES / G1_TN);
        k_gemm1<<<g1, 512, G1_SMEM>>>(h, W2, n_base);
        k_stage2<<<PASS_NODES, 256>>>(h, b2, out, n_base);
    }

    if (out_size > N_EDGES * 64)
        k_dst<<<(N_EDGES + 255) / 256, 256>>>(ei, out);
}

// round 7
// speedup vs baseline: 1.9167x; 1.9167x over previous
#include <cuda_runtime.h>
#include <cuda_fp16.h>
#include <cuda_bf16.h>
#include <cstring>
#include <cstdint>

#define N_NODES 5000
#define N_EDGES 30000
#define HID     64      // hidden
#define ED      16      // edge dim
#define H2      4096    // hidden^2
#define NCOLS   262144  // 4096*64 columns of M

// ---------------- static device scratch (no allocs allowed) ----------------
// Host shadow symbols exist for every __device__ global: keep total < ~1.6 GB
// or the host link fails (GOTPCREL overflow).
#define PASS_NODES 1024
#define N_PASSES   ((N_NODES + PASS_NODES - 1) / PASS_NODES)   // 5
__device__ __align__(16) float g_M[(size_t)PASS_NODES * NCOLS];   // 1.07 GB
__device__ __align__(16) float g_hid[(size_t)N_EDGES * H2];       // 491.5 MB

__device__ int g_off[N_NODES + 1];
__device__ int g_perm[N_EDGES];

// ---------------- fp16 mma helper (legacy path; tcgen05 unavailable:
// harness PTX targets compute_100 without the 'a' feature set) ----------------
__device__ __forceinline__ void mma_f16_k16(float* c,
                                            uint32_t a0, uint32_t a1,
                                            uint32_t a2, uint32_t a3,
                                            uint32_t b0, uint32_t b1) {
    asm volatile(
        "mma.sync.aligned.m16n8k16.row.col.f32.f16.f16.f32 "
        "{%0,%1,%2,%3},{%4,%5,%6,%7},{%8,%9},{%0,%1,%2,%3};"
        : "+f"(c[0]), "+f"(c[1]), "+f"(c[2]), "+f"(c[3])
        : "r"(a0), "r"(a1), "r"(a2), "r"(a3), "r"(b0), "r"(b1));
}

// ---------------- fused single-block CSR build ----------------
__global__ void __launch_bounds__(1024) k_csr(const int* __restrict__ ei) {
    __shared__ int scnt[N_NODES];   // 20 KB
    __shared__ int ts[1024];
    int t = threadIdx.x;

    for (int i = t; i < N_NODES; i += 1024) scnt[i] = 0;
    __syncthreads();
    for (int e = t; e < N_EDGES; e += 1024) atomicAdd(&scnt[ei[e]], 1);
    __syncthreads();

    int c[5];
    int base = t * 5;
    int s = 0;
#pragma unroll
    for (int u = 0; u < 5; u++) {
        int id = base + u;
        c[u] = (id < N_NODES) ? scnt[id] : 0;
        s += c[u];
    }
    ts[t] = s;
    __syncthreads();
    for (int ofs = 1; ofs < 1024; ofs <<= 1) {
        int v = (t >= ofs) ? ts[t - ofs] : 0;
        __syncthreads();
        ts[t] += v;
        __syncthreads();
    }
    int ex = ts[t] - s;
#pragma unroll
    for (int u = 0; u < 5; u++) {
        int id = base + u;
        if (id < N_NODES) { g_off[id] = ex; scnt[id] = ex; }
        ex += c[u];
    }
    if (t == 0) g_off[N_NODES] = N_EDGES;
    __syncthreads();
    for (int e = t; e < N_EDGES; e += 1024) {
        int pos = atomicAdd(&scnt[ei[e]], 1);
        g_perm[pos] = e;
    }
}

// ---------------- hid = relu(edge_attr @ W1 + b1) ----------------
#define HID_EB 8
__global__ void k_hid(const float* __restrict__ ea,
                      const float* __restrict__ W1,
                      const float* __restrict__ b1) {
    __shared__ float eaS[HID_EB][ED];
    int e0 = blockIdx.x * HID_EB;
    int tid = threadIdx.x;
    if (tid < HID_EB * ED) {
        int e = tid / ED, t = tid % ED;
        eaS[e][t] = ea[(size_t)(e0 + e) * ED + t];
    }
    __syncthreads();
    for (int k = tid; k < H2; k += 256) {
        float acc[HID_EB];
        float bv = b1[k];
#pragma unroll
        for (int e = 0; e < HID_EB; e++) acc[e] = bv;
#pragma unroll
        for (int t = 0; t < ED; t++) {
            float w = W1[t * H2 + k];
#pragma unroll
            for (int e = 0; e < HID_EB; e++) acc[e] = fmaf(eaS[e][t], w, acc[e]);
        }
#pragma unroll
        for (int e = 0; e < HID_EB; e++)
            __stcs(&g_hid[(size_t)(e0 + e) * H2 + k], fmaxf(acc[e], 0.0f));
    }
}

// ---------------- GEMM1 (fp16 3-term split, mma.m16n8k16) ----------------
// M[n, c] = sum_j h[n,j] * W2flat[c*64 + j]
//   x = hi + lo (fp16 pair); A*B ~= Ah*Bh + Ah*Bl + Al*Bh  (drop ~2^-22)
// Block tile: 128 nodes x 128 cols, K = 64 (4 k-slabs of 16).
// 256 threads = 8 warps; warp w owns m-tile w (16 rows) x all 16 n-tiles.
// Fragment-ordered smem: one LDS.128 per lane = one full mma fragment.
//   BF[nt16][ks4][lane32] = uint4(b0h, b1h, b0l, b1l)   (f16x2 each) 32 KB
//   AH/AL[mt8][ks4][lane32] = uint4(a0..a3)                       16+16 KB
#define G1_TN 128
#define G1_TC 128
#define OFF_BF 0
#define OFF_AH 32768
#define OFF_AL 49152
#define G1_SMEM 65536

__global__ void __launch_bounds__(256, 3) k_gemm1(const float* __restrict__ h,
                                                  const float* __restrict__ W2,
                                                  int n_base) {
    extern __shared__ __align__(16) char smc[];
    int tid = threadIdx.x;
    int w = tid >> 5, lane = tid & 31;
    int n0 = n_base + blockIdx.y * G1_TN;
    size_t c0 = (size_t)blockIdx.x * G1_TC;

    // ---- fill B fragments: 128 cols x 64 j ----
    for (int idx = tid; idx < G1_TC * 64; idx += 256) {
        int c = idx >> 6, j = idx & 63;
        float v = W2[(c0 + c) * 64 + j];
        __half hi = __float2half_rn(v);
        __half lo = __float2half_rn(v - __half2float(hi));
        int nt = c >> 3, colin = c & 7;
        int ks = j >> 4, kk = j & 15;
        int flane = colin * 4 + ((kk & 7) >> 1);
        int reg = kk >> 3;            // b0 or b1
        int half_sel = kk & 1;
        uint32_t off = (uint32_t)(((nt * 4 + ks) * 32 + flane) * 16 + reg * 4 +
                                  half_sel * 2);
        *(__half*)(smc + OFF_BF + off) = hi;        // slots 0,1 = hi
        *(__half*)(smc + OFF_BF + off + 8) = lo;    // slots 2,3 = lo
    }
    // ---- fill A fragments: 128 nodes x 64 j ----
    for (int idx = tid; idx < G1_TN * 64; idx += 256) {
        int m = idx >> 6, j = idx & 63;
        int n = n0 + m;
        float v = (n < N_NODES) ? h[(size_t)n * 64 + j] : 0.0f;
        __half hi = __float2half_rn(v);
        __half lo = __float2half_rn(v - __half2float(hi));
        int mt = m >> 4, mm = m & 15;
        int ks = j >> 4, kk = j & 15;
        int flane = (mm & 7) * 4 + ((kk & 7) >> 1);
        int reg = (mm >> 3) | ((kk >> 3) << 1);     // a0..a3
        int half_sel = kk & 1;
        uint32_t off = (uint32_t)(((mt * 4 + ks) * 32 + flane) * 16 + reg * 4 +
                                  half_sel * 2);
        *(__half*)(smc + OFF_AH + off) = hi;
        *(__half*)(smc + OFF_AL + off) = lo;
    }
    __syncthreads();

    float acc[16][4];
#pragma unroll
    for (int nt = 0; nt < 16; nt++)
#pragma unroll
        for (int r = 0; r < 4; r++) acc[nt][r] = 0.0f;

#pragma unroll
    for (int ks = 0; ks < 4; ks++) {
        uint4 ah = *(const uint4*)(smc + OFF_AH + ((w * 4 + ks) * 32 + lane) * 16);
        uint4 al = *(const uint4*)(smc + OFF_AL + ((w * 4 + ks) * 32 + lane) * 16);
#pragma unroll
        for (int nt = 0; nt < 16; nt++) {
            uint4 b = *(const uint4*)(smc + OFF_BF + ((nt * 4 + ks) * 32 + lane) * 16);
            mma_f16_k16(acc[nt], ah.x, ah.y, ah.z, ah.w, b.x, b.y);   // Ah*Bh
            mma_f16_k16(acc[nt], ah.x, ah.y, ah.z, ah.w, b.z, b.w);   // Ah*Bl
            mma_f16_k16(acc[nt], al.x, al.y, al.z, al.w, b.x, b.y);   // Al*Bh
        }
    }

    // ---- epilogue: streaming float2 stores to g_M ----
    int r = lane >> 2, cq = (lane & 3) * 2;
    int row0 = (n0 - n_base) + w * 16 + r;      // local row in pass
#pragma unroll
    for (int nt = 0; nt < 16; nt++) {
        size_t col = c0 + nt * 8 + cq;
        float* p0 = g_M + (size_t)row0 * NCOLS + col;
        __stcs((float2*)p0, make_float2(acc[nt][0], acc[nt][1]));
        __stcs((float2*)(p0 + (size_t)8 * NCOLS),
               make_float2(acc[nt][2], acc[nt][3]));
    }
}

// ---------------- Stage 2: m[e,i] = sum_k hid[e,k]*M[n,k*64+i] + cb[i] ----------------
#define S2_BODY(NACC)                                                         \
    _Pragma("unroll 4")                                                       \
    for (int k = 0; k < 128; k++) {                                           \
        float2 mm = *(const float2*)&Ms[k * 64 + i2];                         \
        float h0 = hidS[s * 128 + k];                                         \
        a0.x = fmaf(h0, mm.x, a0.x);                                          \
        a0.y = fmaf(h0, mm.y, a0.y);                                          \
        if (NACC > 1) {                                                       \
            float h1 = hidS[(s + 8) * 128 + k];                               \
            a1.x = fmaf(h1, mm.x, a1.x);                                      \
            a1.y = fmaf(h1, mm.y, a1.y);                                      \
        }                                                                     \
        if (NACC > 2) {                                                       \
            float h2v = hidS[(s + 16) * 128 + k];                             \
            a2.x = fmaf(h2v, mm.x, a2.x);                                     \
            a2.y = fmaf(h2v, mm.y, a2.y);                                     \
        }                                                                     \
    }

__global__ void __launch_bounds__(256) k_stage2(const float* __restrict__ h,
                                                const float* __restrict__ b2,
                                                float* __restrict__ out,
                                                int n_base) {
    __shared__ __align__(16) float Ms[128 * 64];
    __shared__ __align__(16) float hidS[24 * 128];
    __shared__ float hS[64];
    __shared__ float cb[64];
    __shared__ int eS[24];

    int n = n_base + blockIdx.x;
    if (n >= N_NODES) return;
    int start = g_off[n], end = g_off[n + 1];
    if (start == end) return;

    int tid = threadIdx.x;
    int s = tid >> 5;
    int il = tid & 31;
    int i2 = il * 2;

    if (tid < 64) hS[tid] = h[(size_t)n * 64 + tid];
    __syncthreads();
    if (s == 0) {
        float c0 = 0.f, c1 = 0.f;
#pragma unroll 8
        for (int j = 0; j < 64; j++) {
            float hv = hS[j];
            c0 = fmaf(b2[i2 * 64 + j], hv, c0);
            c1 = fmaf(b2[(i2 + 1) * 64 + j], hv, c1);
        }
        cb[i2] = c0; cb[i2 + 1] = c1;
    }

    const float* Mrow = g_M + (size_t)(n - n_base) * NCOLS;

    for (int base = start; base < end; base += 24) {
        int cnt = min(24, end - base);
        __syncthreads();
        if (tid < cnt) eS[tid] = g_perm[base + tid];
        __syncthreads();

        float2 a0 = make_float2(cb[i2], cb[i2 + 1]);
        float2 a1 = a0, a2 = a0;
        int nacc = (s < cnt) + (s + 8 < cnt) + (s + 16 < cnt);

        for (int kc = 0; kc < 32; kc++) {
            __syncthreads();
            const float4* msrc = (const float4*)(Mrow + (size_t)kc * 8192);
            for (int u = tid; u < 2048; u += 256)
                ((float4*)Ms)[u] = __ldcs(msrc + u);
            for (int u = tid; u < cnt * 32; u += 256) {
                int v = u >> 5, q = u & 31;
                const float4* hsrc =
                    (const float4*)(g_hid + (size_t)eS[v] * H2 + kc * 128);
                ((float4*)(hidS + v * 128))[q] = __ldcs(hsrc + q);
            }
            __syncthreads();
            switch (nacc) {
                case 1: { S2_BODY(1) } break;
                case 2: { S2_BODY(2) } break;
                case 3: { S2_BODY(3) } break;
                default: break;
            }
        }
        if (nacc > 0) *(float2*)&out[(size_t)eS[s] * 64 + i2] = a0;
        if (nacc > 1) *(float2*)&out[(size_t)eS[s + 8] * 64 + i2] = a1;
        if (nacc > 2) *(float2*)&out[(size_t)eS[s + 16] * 64 + i2] = a2;
    }
}

// ---------------- dst passthrough ----------------
__global__ void k_dst(const int* __restrict__ ei, float* __restrict__ out) {
    int e = blockIdx.x * blockDim.x + threadIdx.x;
    if (e < N_EDGES) out[(size_t)N_EDGES * 64 + e] = (float)ei[N_EDGES + e];
}

// ---------------- launch ----------------
extern "C" void kernel_launch(void* const* d_in, const int* in_sizes, int n_in,
                              void* d_out, int out_size) {
    const float* h  = (const float*)d_in[0];
    const int*   ei = (const int*)d_in[1];
    const float* ea = (const float*)d_in[2];
    const float* W1 = (const float*)d_in[3];
    const float* b1 = (const float*)d_in[4];
    const float* W2 = (const float*)d_in[5];
    const float* b2 = (const float*)d_in[6];
    float* out = (float*)d_out;

    k_csr<<<1, 1024>>>(ei);
    k_hid<<<N_EDGES / HID_EB, 256>>>(ea, W1, b1);

    cudaFuncSetAttribute(k_gemm1, cudaFuncAttributeMaxDynamicSharedMemorySize,
                         G1_SMEM);

    for (int p = 0; p < N_PASSES; p++) {
        int n_base = p * PASS_NODES;
        dim3 g1(NCOLS / G1_TC, PASS_NODES / G1_TN);
        k_gemm1<<<g1, 256, G1_SMEM>>>(h, W2, n_base);
        k_stage2<<<PASS_NODES, 256>>>(h, b2, out, n_base);
    }

    if (out_size > N_EDGES * 64)
        k_dst<<<(N_EDGES + 255) / 256, 256>>>(ei, out);
}